// round 9
// baseline (speedup 1.0000x reference)
#include <cuda_runtime.h>
#include <cuda_bf16.h>
#include <cstdint>

#define DIM 512
#define NH 8
#define HD 64
#define MAXM 8192
#define KTOT 512

// ---------------------------------------------------------------------------
// Scratch (allocation-free rule: __device__ globals)
// ---------------------------------------------------------------------------
__device__ uint32_t g_xt[MAXM * DIM];
__device__ uint32_t g_wqt[3 * DIM * DIM];
__device__ uint32_t g_wpt[DIM * DIM];
__device__ uint32_t g_qt[MAXM * DIM];            // q head-major, x hd^-.5*log2e
__device__ uint32_t g_kt[MAXM * DIM];
__device__ __nv_bfloat16 g_vhi[MAXM * DIM], g_vlo[MAXM * DIM];
__device__ uint32_t g_at[MAXM * DIM];            // attn out, tf32, sigma-perm

// ---------------------------------------------------------------------------
// helpers (compute_103-safe: sm_80 baseline PTX)
// ---------------------------------------------------------------------------
__device__ __forceinline__ uint32_t smem_u32(const void* p) {
    uint32_t a;
    asm("{ .reg .u64 t; cvta.to.shared.u64 t, %1; cvt.u32.u64 %0, t; }"
        : "=r"(a) : "l"(p));
    return a;
}
__device__ __forceinline__ uint32_t tf32r(float v) {
    uint32_t r;
    asm("cvt.rna.tf32.f32 %0, %1;" : "=r"(r) : "f"(v));
    return r;
}
__device__ __forceinline__ float ex2f(float x) {
    float r;
    asm("ex2.approx.f32 %0, %1;" : "=f"(r) : "f"(x));
    return r;
}
__device__ __forceinline__ int sig16(int k) {
    return (k & ~15) | (((k & 3) << 2) | ((k >> 2) & 3));
}
__device__ __forceinline__ void mmatf(float* c, uint32_t a0, uint32_t a1,
                                      uint32_t a2, uint32_t a3,
                                      uint32_t b0, uint32_t b1) {
    asm volatile(
        "mma.sync.aligned.m16n8k8.row.col.f32.tf32.tf32.f32 "
        "{%0,%1,%2,%3}, {%4,%5,%6,%7}, {%8,%9}, {%0,%1,%2,%3};"
        : "+f"(c[0]), "+f"(c[1]), "+f"(c[2]), "+f"(c[3])
        : "r"(a0), "r"(a1), "r"(a2), "r"(a3), "r"(b0), "r"(b1));
}
__device__ __forceinline__ void ldsm4t(uint32_t* r, uint32_t addr) {
    asm volatile("ldmatrix.sync.aligned.m8n8.x4.trans.shared.b16 {%0,%1,%2,%3}, [%4];"
                 : "=r"(r[0]), "=r"(r[1]), "=r"(r[2]), "=r"(r[3]) : "r"(addr));
}
__device__ __forceinline__ void mma16816(float* c, const uint32_t* a,
                                         const uint32_t* b) {
    asm volatile(
        "mma.sync.aligned.m16n8k16.row.col.f32.bf16.bf16.f32 "
        "{%0,%1,%2,%3}, {%4,%5,%6,%7}, {%8,%9}, {%0,%1,%2,%3};"
        : "+f"(c[0]), "+f"(c[1]), "+f"(c[2]), "+f"(c[3])
        : "r"(a[0]), "r"(a[1]), "r"(a[2]), "r"(a[3]), "r"(b[0]), "r"(b[1]));
}
__device__ __forceinline__ void split2(float a, float b, uint32_t& uhi, uint32_t& ulo) {
    __nv_bfloat162 hh = __floats2bfloat162_rn(a, b);
    __nv_bfloat162 ll = __floats2bfloat162_rn(a - __bfloat162float(hh.x),
                                              b - __bfloat162float(hh.y));
    uhi = *(uint32_t*)&hh;
    ulo = *(uint32_t*)&ll;
}
__device__ __forceinline__ void cpa16(uint32_t saddr, const void* g) {
    asm volatile("cp.async.cg.shared.global [%0], [%1], 16;"
                 :: "r"(saddr), "l"(g) : "memory");
}
#define CPA_COMMIT() asm volatile("cp.async.commit_group;" ::: "memory")
#define CPA_WAIT1()  asm volatile("cp.async.wait_group 1;" ::: "memory")
#define CPA_WAIT0()  asm volatile("cp.async.wait_group 0;" ::: "memory")

// ---------------------------------------------------------------------------
// Prep: fp32 -> tf32 (rna), sigma-permuted k index
// ---------------------------------------------------------------------------
__global__ void prep(const float* __restrict__ x, const float* __restrict__ wq,
                     const float* __restrict__ wp, int nx) {
    const int NWQ = 3 * DIM * DIM, NWP = DIM * DIM;
    int i = blockIdx.x * 256 + threadIdx.x;
    float v;
    uint32_t* out;
    int j;
    if (i < nx)                  { v = x[i];            out = g_xt;  j = i; }
    else if (i < nx + NWQ)       { j = i - nx;       v = wq[j]; out = g_wqt; }
    else if (i < nx + NWQ + NWP) { j = i - nx - NWQ; v = wp[j]; out = g_wpt; }
    else return;
    out[sig16(j)] = tf32r(v);
}

// ---------------------------------------------------------------------------
// TF32 GEMM, 128 threads, CTA tile 128(M) x 64(N), warp tile 32x64,
// K chunk 32, 2-stage cp.async pipeline, 4 CTAs/SM target.
// ---------------------------------------------------------------------------
#define GSTG2 24576
#define GEMM_SMEM (2 * GSTG2)
#define NCHUNK (KTOT / 32)
#define QSCALE (0.125f * 1.4426950408889634f)

template<int MODE>
__global__ __launch_bounds__(128, 4)
void gemm_tc(float* __restrict__ C, int M, int NC,
             const int* __restrict__ Hp, const int* __restrict__ Wp)
{
    extern __shared__ __align__(16) char dsm[];
    const uint32_t smb = smem_u32(dsm);

    const int tid = threadIdx.x;
    const int wid = tid >> 5;
    const int lane = tid & 31;
    const int gID = lane >> 2, cA = lane & 3;

    const int m0 = blockIdx.y * 128;
    const int n0 = blockIdx.x * 64;

    const uint32_t* A = MODE ? g_at : g_xt;
    const uint32_t* B = MODE ? g_wpt : g_wqt;

    auto issue = [&](int stg, int chunk) {
        const uint32_t sb = smb + stg * GSTG2;
        const int k0 = chunk * 32;
#pragma unroll
        for (int t = 0; t < 8; t++) {
            int idx = t * 128 + tid;
            int row = idx >> 3, u = idx & 7;
            uint32_t so = (uint32_t)row * 128 + ((u + 4 * row) & 7) * 16;
            cpa16(sb + so, A + (size_t)(m0 + row) * KTOT + k0 + u * 4);
        }
#pragma unroll
        for (int t = 0; t < 4; t++) {
            int idx = t * 128 + tid;
            int row = idx >> 3, u = idx & 7;
            uint32_t so = (uint32_t)row * 128 + ((u + 4 * row) & 7) * 16;
            cpa16(sb + 16384 + so, B + (size_t)(n0 + row) * KTOT + k0 + u * 4);
        }
        CPA_COMMIT();
    };

    float acc[2][8][4];
#pragma unroll
    for (int i = 0; i < 2; i++)
#pragma unroll
        for (int j = 0; j < 8; j++)
#pragma unroll
            for (int k = 0; k < 4; k++) acc[i][j][k] = 0.f;

    issue(0, 0);

    for (int chunk = 0; chunk < NCHUNK; chunk++) {
        if (chunk + 1 < NCHUNK) { issue((chunk + 1) & 1, chunk + 1); CPA_WAIT1(); }
        else                    { CPA_WAIT0(); }
        __syncthreads();

        const char* aC = dsm + (chunk & 1) * GSTG2;
        const char* bC = aC + 16384;

#pragma unroll
        for (int g = 0; g < 2; g++) {
            uint4 alo[2], ahi[2];
#pragma unroll
            for (int mt = 0; mt < 2; mt++) {
                int rA = wid * 32 + mt * 16 + gID;
                uint32_t u = (uint32_t)((g * 4 + cA + 4 * rA) & 7) * 16;
                alo[mt] = *(const uint4*)(aC + rA * 128 + u);
                ahi[mt] = *(const uint4*)(aC + (rA + 8) * 128 + u);
            }
#pragma unroll
            for (int ng = 0; ng < 8; ng++) {
                int rB = ng * 8 + gID;
                uint32_t u = (uint32_t)((g * 4 + cA + 4 * rB) & 7) * 16;
                uint4 bb = *(const uint4*)(bC + rB * 128 + u);
#pragma unroll
                for (int mt = 0; mt < 2; mt++) {
                    mmatf(acc[mt][ng], alo[mt].x, ahi[mt].x, alo[mt].y, ahi[mt].y,
                          bb.x, bb.y);
                    mmatf(acc[mt][ng], alo[mt].z, ahi[mt].z, alo[mt].w, ahi[mt].w,
                          bb.z, bb.w);
                }
            }
        }
        __syncthreads();
    }

    // ---------------- epilogue ----------------
    int Nseq = 0;
    if (MODE == 0) Nseq = (*Wp) * (*Hp);

#pragma unroll
    for (int mt = 0; mt < 2; mt++) {
#pragma unroll
        for (int ro = 0; ro < 2; ro++) {
            const int m = m0 + wid * 32 + mt * 16 + ro * 8 + gID;
            int b = 0, n = 0;
            if (MODE == 0) { b = m / Nseq; n = m - b * Nseq; }
#pragma unroll
            for (int nt = 0; nt < 8; nt++) {
                const int d = n0 + nt * 8 + cA * 2;
                float a0 = acc[mt][nt][ro * 2 + 0];
                float a1 = acc[mt][nt][ro * 2 + 1];
                if (MODE == 0) {
                    const int which = d >> 9;
                    const int h = (d >> 6) & 7;
                    const int e = d & 63;
                    size_t off = ((size_t)(b * NH + h) * Nseq + n) * HD;
                    if (which == 0) {
                        g_qt[off + sig16(e)]     = tf32r(a0 * QSCALE);
                        g_qt[off + sig16(e + 1)] = tf32r(a1 * QSCALE);
                    } else if (which == 1) {
                        g_kt[off + sig16(e)]     = tf32r(a0);
                        g_kt[off + sig16(e + 1)] = tf32r(a1);
                    } else {
                        uint32_t uh, ul;
                        split2(a0, a1, uh, ul);
                        *(uint32_t*)(g_vhi + off + e) = uh;
                        *(uint32_t*)(g_vlo + off + e) = ul;
                    }
                } else {
                    *(float2*)(C + (size_t)m * NC + d) = make_float2(a0, a1);
                }
            }
        }
    }
}

// ---------------------------------------------------------------------------
// Flash attention, 128 threads, 128 Q rows per CTA: each warp owns TWO
// 16-row Q blocks processed back-to-back per K/V tile (halves K/V traffic,
// doubles tensor work per sync). 2-stage cp.async K/V pipeline, 2 CTAs/SM.
// ---------------------------------------------------------------------------
#define VHOFF 16384
#define VLOFF 25600
#define ASTG2 34816
#define ASTR 72
#define ATTN_SMEM (2 * ASTG2 + 256 + 512 + 512)

__global__ __launch_bounds__(128, 2)
void attn_mma(const float* __restrict__ log_decay, int M,
              const int* __restrict__ Hp, const int* __restrict__ Wp)
{
    extern __shared__ __align__(16) char sm[];
    const uint32_t smb = smem_u32(sm);
    float* Ts  = (float*)(sm + 2 * ASTG2);
    int*   krs = (int*)(sm + 2 * ASTG2 + 256);
    int*   kcs = (int*)(sm + 2 * ASTG2 + 768);

    const int Wv = *Wp, Hv = *Hp;
    const int Nseq = Wv * Hv;
    const int ntiles = Nseq / 64;
    const bool fast = (Wv == 32);
    const int h = blockIdx.y;
    const int m0 = blockIdx.x * 128;
    const int b = m0 / Nseq;
    const int n0 = m0 - b * Nseq;

    const int tid = threadIdx.x, w = tid >> 5, lane = tid & 31;
    const int gID = lane >> 2, cA = lane & 3, t2 = cA * 2;

    const float decay = log1pf(__expf(log_decay[h]));
    if (tid < 64) Ts[tid] = __expf(-decay * (float)tid);

    const size_t bh_off = (size_t)(b * NH + h) * Nseq * HD;
    const uint32_t* Qt_g = g_qt + bh_off + (size_t)n0 * HD;
    const uint32_t* Kt_g = g_kt + bh_off;
    const __nv_bfloat16* Vh_g = g_vhi + bh_off;
    const __nv_bfloat16* Vl_g = g_vlo + bh_off;

    // per-half query grid coords (half hh covers rows hh*64 .. hh*64+63)
    int qrA[2], qcA[2], qrB[2], qcB[2];
#pragma unroll
    for (int hh = 0; hh < 2; hh++) {
        int nrA = n0 + hh * 64 + w * 16 + gID;
        qrA[hh] = nrA / Wv; qcA[hh] = nrA - qrA[hh] * Wv;
        int nrB = nrA + 8;
        qrB[hh] = nrB / Wv; qcB[hh] = nrB - qrB[hh] * Wv;
    }

    // ---- stage Q (128 rows x 16 units, swizzled; aliases stage-0) ----
#pragma unroll
    for (int i = 0; i < 16; i++) {
        int idx = i * 128 + tid;
        int row = idx >> 4, u = idx & 15;
        cpa16(smb + (uint32_t)row * 256 + ((u + 4 * row) & 15) * 16,
              Qt_g + (size_t)row * HD + u * 4);
    }
    CPA_COMMIT();
    CPA_WAIT0();
    __syncthreads();

    // ---- Q fragments (persistent, tf32, both halves) ----
    uint4 qlo[2][4], qhi[2][4];
#pragma unroll
    for (int hh = 0; hh < 2; hh++) {
        const int r0 = hh * 64 + w * 16 + gID;
#pragma unroll
        for (int g = 0; g < 4; g++) {
            uint32_t u = (uint32_t)((g * 4 + cA + 4 * r0) & 15) * 16;
            qlo[hh][g] = *(const uint4*)(sm + r0 * 256 + u);
            qhi[hh][g] = *(const uint4*)(sm + (r0 + 8) * 256 + u);
        }
    }

    // ---- per-thread column decay factors (W==32: same for both halves) ----
    float tcA[8], tcB[8];
#pragma unroll
    for (int j = 0; j < 8; j++) {
        int kcol = (j >> 1) * 8 + t2 + (j & 1);
        tcA[j] = Ts[abs(qcA[0] - kcol)];
        tcB[j] = Ts[abs(qcB[0] - kcol)];
    }
    __syncthreads();   // Q frag / Ts reads done before stage-0 overwrite

    auto issue_kv = [&](int stg, int t0) {
        const uint32_t sb = smb + stg * ASTG2;
#pragma unroll
        for (int i = 0; i < 8; i++) {
            int idx = i * 128 + tid;
            int row = idx >> 4, u = idx & 15;
            cpa16(sb + (uint32_t)row * 256 + ((u + 4 * row) & 15) * 16,
                  Kt_g + (size_t)(t0 + row) * HD + u * 4);
        }
#pragma unroll
        for (int i = 0; i < 4; i++) {
            int idx = i * 128 + tid;
            int row = idx >> 3, c8 = idx & 7;
            uint32_t so = (uint32_t)row * 144 + c8 * 16;
            size_t go = (size_t)(t0 + row) * HD + c8 * 8;
            cpa16(sb + VHOFF + so, Vh_g + go);
            cpa16(sb + VLOFF + so, Vl_g + go);
        }
        if (!fast && tid < 64) {
            int kn = t0 + tid;
            int kr = kn / Wv;
            krs[stg * 64 + tid] = kr;
            kcs[stg * 64 + tid] = kn - kr * Wv;
        }
        CPA_COMMIT();
    };

    float o[2][8][4];
#pragma unroll
    for (int hh = 0; hh < 2; hh++)
#pragma unroll
        for (int i = 0; i < 8; i++)
#pragma unroll
            for (int j = 0; j < 4; j++) o[hh][i][j] = 0.f;
    float lsA[2] = {0.f, 0.f}, lsB[2] = {0.f, 0.f};

    const uint32_t vrow_l = (lane & 7) + ((lane >> 3) & 1) * 8;
    const uint32_t vcol_l = (lane >> 4) * 8;

    issue_kv(0, 0);

    for (int it = 0; it < ntiles; it++) {
        const int t0 = it * 64;
        if (it + 1 < ntiles) { issue_kv((it + 1) & 1, t0 + 64); CPA_WAIT1(); }
        else                 { CPA_WAIT0(); }
        __syncthreads();

        const uint32_t sb = smb + (it & 1) * ASTG2;
        const char* sbc = sm + (it & 1) * ASTG2;
        const int r0t = t0 >> 5;

#pragma unroll
        for (int hh = 0; hh < 2; hh++) {
            // ---- S = Q K^T (tf32, scores pre-scaled by log2e) ----
            float s[8][4];
#pragma unroll
            for (int i = 0; i < 8; i++)
#pragma unroll
                for (int j = 0; j < 4; j++) s[i][j] = 0.f;

#pragma unroll
            for (int g = 0; g < 4; g++) {
#pragma unroll
                for (int ng = 0; ng < 8; ng++) {
                    int rb = ng * 8 + gID;
                    uint32_t u = (uint32_t)((g * 4 + cA + 4 * rb) & 15) * 16;
                    uint4 kb = *(const uint4*)(sbc + rb * 256 + u);
                    mmatf(s[ng], qlo[hh][g].x, qhi[hh][g].x,
                          qlo[hh][g].y, qhi[hh][g].y, kb.x, kb.y);
                    mmatf(s[ng], qlo[hh][g].z, qhi[hh][g].z,
                          qlo[hh][g].w, qhi[hh][g].w, kb.z, kb.w);
                }
            }

            // ---- bias + exp + bf16 split pack ----
            uint32_t phi2[16], plo2[16];
            if (fast) {
                const float trA0 = Ts[abs(qrA[hh] - r0t)];
                const float trA1 = Ts[abs(qrA[hh] - r0t - 1)];
                const float trB0 = Ts[abs(qrB[hh] - r0t)];
                const float trB1 = Ts[abs(qrB[hh] - r0t - 1)];
#pragma unroll
                for (int nt = 0; nt < 8; nt++) {
                    const int jj = (nt & 3) * 2;
                    const float f0 = (nt < 4) ? trA0 : trA1;
                    const float f1 = (nt < 4) ? trB0 : trB1;
                    float p00 = ex2f(s[nt][0]) * (tcA[jj]     * f0);
                    float p01 = ex2f(s[nt][1]) * (tcA[jj + 1] * f0);
                    float p10 = ex2f(s[nt][2]) * (tcB[jj]     * f1);
                    float p11 = ex2f(s[nt][3]) * (tcB[jj + 1] * f1);
                    lsA[hh] += p00 + p01;
                    lsB[hh] += p10 + p11;
                    split2(p00, p01, phi2[nt * 2 + 0], plo2[nt * 2 + 0]);
                    split2(p10, p11, phi2[nt * 2 + 1], plo2[nt * 2 + 1]);
                }
            } else {
                const int* kr_t = krs + (it & 1) * 64;
                const int* kc_t = kcs + (it & 1) * 64;
#pragma unroll
                for (int nt = 0; nt < 8; nt++) {
                    const int c0 = nt * 8 + t2, c1 = c0 + 1;
                    const int kr0 = kr_t[c0], kc0 = kc_t[c0];
                    const int kr1 = kr_t[c1], kc1 = kc_t[c1];
                    float p00 = ex2f(s[nt][0]) * Ts[abs(qrA[hh] - kr0) + abs(qcA[hh] - kc0)];
                    float p01 = ex2f(s[nt][1]) * Ts[abs(qrA[hh] - kr1) + abs(qcA[hh] - kc1)];
                    float p10 = ex2f(s[nt][2]) * Ts[abs(qrB[hh] - kr0) + abs(qcB[hh] - kc0)];
                    float p11 = ex2f(s[nt][3]) * Ts[abs(qrB[hh] - kr1) + abs(qcB[hh] - kc1)];
                    lsA[hh] += p00 + p01;
                    lsB[hh] += p10 + p11;
                    split2(p00, p01, phi2[nt * 2 + 0], plo2[nt * 2 + 0]);
                    split2(p10, p11, phi2[nt * 2 + 1], plo2[nt * 2 + 1]);
                }
            }

            // ---- O += P V (bf16 3-term) ----
#pragma unroll
            for (int g = 0; g < 4; g++) {
                const uint32_t* pah = &phi2[4 * g];
                const uint32_t* pal = &plo2[4 * g];
#pragma unroll
                for (int ntp = 0; ntp < 4; ntp++) {
                    uint32_t off = ((16u * g + vrow_l) * ASTR + 16 * ntp + vcol_l) * 2;
                    uint32_t vbh[4], vbl[4];
                    ldsm4t(vbh, sb + VHOFF + off);
                    ldsm4t(vbl, sb + VLOFF + off);
                    mma16816(o[hh][2 * ntp],     pah, vbh);
                    mma16816(o[hh][2 * ntp],     pah, vbl);
                    mma16816(o[hh][2 * ntp],     pal, vbh);
                    mma16816(o[hh][2 * ntp + 1], pah, vbh + 2);
                    mma16816(o[hh][2 * ntp + 1], pah, vbl + 2);
                    mma16816(o[hh][2 * ntp + 1], pal, vbh + 2);
                }
            }
        }
        __syncthreads();
    }

    // ---- normalize + write tf32 sigma-perm ----
#pragma unroll
    for (int hh = 0; hh < 2; hh++) {
        float l0 = lsA[hh], l1 = lsB[hh];
        l0 += __shfl_xor_sync(0xFFFFFFFFu, l0, 1);
        l0 += __shfl_xor_sync(0xFFFFFFFFu, l0, 2);
        l1 += __shfl_xor_sync(0xFFFFFFFFu, l1, 1);
        l1 += __shfl_xor_sync(0xFFFFFFFFu, l1, 2);
        const float inv0 = 1.f / l0, inv1 = 1.f / l1;

        const size_t rb0 = (size_t)(m0 + hh * 64 + w * 16 + gID) * DIM;
        const size_t rb1 = rb0 + 8 * DIM;
#pragma unroll
        for (int nt = 0; nt < 8; nt++) {
            const int col = h * HD + nt * 8 + t2;
            g_at[rb0 + sig16(col)]     = tf32r(o[hh][nt][0] * inv0);
            g_at[rb0 + sig16(col + 1)] = tf32r(o[hh][nt][1] * inv0);
            g_at[rb1 + sig16(col)]     = tf32r(o[hh][nt][2] * inv1);
            g_at[rb1 + sig16(col + 1)] = tf32r(o[hh][nt][3] * inv1);
        }
    }
}

// ---------------------------------------------------------------------------
extern "C" void kernel_launch(void* const* d_in, const int* in_sizes, int n_in,
                              void* d_out, int out_size)
{
    const float* x      = (const float*)d_in[0];
    const float* w_qkv  = (const float*)d_in[1];
    const float* w_proj = (const float*)d_in[2];
    const float* ldec   = (const float*)d_in[3];
    const int* Hp = (const int*)d_in[4];
    const int* Wp = (const int*)d_in[5];

    const int M = in_sizes[0] / DIM;

    cudaFuncSetAttribute(gemm_tc<0>, cudaFuncAttributeMaxDynamicSharedMemorySize, GEMM_SMEM);
    cudaFuncSetAttribute(gemm_tc<1>, cudaFuncAttributeMaxDynamicSharedMemorySize, GEMM_SMEM);
    cudaFuncSetAttribute(attn_mma,   cudaFuncAttributeMaxDynamicSharedMemorySize, ATTN_SMEM);

    // 0) fp32 -> tf32 (sigma-permuted)
    {
        int total = M * DIM + 3 * DIM * DIM + DIM * DIM;
        prep<<<(total + 255) / 256, 256>>>(x, w_qkv, w_proj, M * DIM);
    }
    // 1) QKV projection (tf32) -> split q/k/v head-major
    gemm_tc<0><<<dim3(3 * DIM / 64, M / 128), 128, GEMM_SMEM>>>(nullptr, M, 3 * DIM, Hp, Wp);
    // 2) spatial-decay flash attention (128 Q rows / CTA)
    attn_mma<<<dim3(M / 128, NH), 128, ATTN_SMEM>>>(ldec, M, Hp, Wp);
    // 3) output projection (tf32)
    gemm_tc<1><<<dim3(DIM / 64, M / 128), 128, GEMM_SMEM>>>((float*)d_out, M, DIM,
                                                            nullptr, nullptr);
}

// round 10
// speedup vs baseline: 1.1752x; 1.1752x over previous
#include <cuda_runtime.h>
#include <cuda_bf16.h>
#include <cstdint>

#define DIM 512
#define NH 8
#define HD 64
#define MAXM 8192
#define KTOT 512

// ---------------------------------------------------------------------------
// Scratch (allocation-free rule: __device__ globals)
// ---------------------------------------------------------------------------
__device__ uint32_t g_xt[MAXM * DIM];
__device__ uint32_t g_wqt[3 * DIM * DIM];
__device__ uint32_t g_wpt[DIM * DIM];
__device__ uint32_t g_qt[MAXM * DIM];            // q head-major, x hd^-.5*log2e
__device__ uint32_t g_kt[MAXM * DIM];
__device__ __nv_bfloat16 g_vhi[MAXM * DIM], g_vlo[MAXM * DIM];
__device__ uint32_t g_at[MAXM * DIM];            // attn out, tf32, sigma-perm

// ---------------------------------------------------------------------------
// helpers (compute_103-safe: sm_80 baseline PTX)
// ---------------------------------------------------------------------------
__device__ __forceinline__ uint32_t smem_u32(const void* p) {
    uint32_t a;
    asm("{ .reg .u64 t; cvta.to.shared.u64 t, %1; cvt.u32.u64 %0, t; }"
        : "=r"(a) : "l"(p));
    return a;
}
__device__ __forceinline__ uint32_t tf32r(float v) {
    uint32_t r;
    asm("cvt.rna.tf32.f32 %0, %1;" : "=r"(r) : "f"(v));
    return r;
}
__device__ __forceinline__ float ex2f(float x) {
    float r;
    asm("ex2.approx.f32 %0, %1;" : "=f"(r) : "f"(x));
    return r;
}
__device__ __forceinline__ int sig16(int k) {
    return (k & ~15) | (((k & 3) << 2) | ((k >> 2) & 3));
}
__device__ __forceinline__ void mmatf(float* c, uint32_t a0, uint32_t a1,
                                      uint32_t a2, uint32_t a3,
                                      uint32_t b0, uint32_t b1) {
    asm volatile(
        "mma.sync.aligned.m16n8k8.row.col.f32.tf32.tf32.f32 "
        "{%0,%1,%2,%3}, {%4,%5,%6,%7}, {%8,%9}, {%0,%1,%2,%3};"
        : "+f"(c[0]), "+f"(c[1]), "+f"(c[2]), "+f"(c[3])
        : "r"(a0), "r"(a1), "r"(a2), "r"(a3), "r"(b0), "r"(b1));
}
__device__ __forceinline__ void ldsm4t(uint32_t* r, uint32_t addr) {
    asm volatile("ldmatrix.sync.aligned.m8n8.x4.trans.shared.b16 {%0,%1,%2,%3}, [%4];"
                 : "=r"(r[0]), "=r"(r[1]), "=r"(r[2]), "=r"(r[3]) : "r"(addr));
}
__device__ __forceinline__ void mma16816(float* c, const uint32_t* a,
                                         const uint32_t* b) {
    asm volatile(
        "mma.sync.aligned.m16n8k16.row.col.f32.bf16.bf16.f32 "
        "{%0,%1,%2,%3}, {%4,%5,%6,%7}, {%8,%9}, {%0,%1,%2,%3};"
        : "+f"(c[0]), "+f"(c[1]), "+f"(c[2]), "+f"(c[3])
        : "r"(a[0]), "r"(a[1]), "r"(a[2]), "r"(a[3]), "r"(b[0]), "r"(b[1]));
}
__device__ __forceinline__ void split2(float a, float b, uint32_t& uhi, uint32_t& ulo) {
    __nv_bfloat162 hh = __floats2bfloat162_rn(a, b);
    __nv_bfloat162 ll = __floats2bfloat162_rn(a - __bfloat162float(hh.x),
                                              b - __bfloat162float(hh.y));
    uhi = *(uint32_t*)&hh;
    ulo = *(uint32_t*)&ll;
}
__device__ __forceinline__ void cpa16(uint32_t saddr, const void* g) {
    asm volatile("cp.async.cg.shared.global [%0], [%1], 16;"
                 :: "r"(saddr), "l"(g) : "memory");
}
#define CPA_COMMIT() asm volatile("cp.async.commit_group;" ::: "memory")
#define CPA_WAIT1()  asm volatile("cp.async.wait_group 1;" ::: "memory")
#define CPA_WAIT0()  asm volatile("cp.async.wait_group 0;" ::: "memory")

// ---------------------------------------------------------------------------
// Prep: fp32 -> tf32 (rna), sigma-permuted k index
// ---------------------------------------------------------------------------
__global__ void prep(const float* __restrict__ x, const float* __restrict__ wq,
                     const float* __restrict__ wp, int nx) {
    const int NWQ = 3 * DIM * DIM, NWP = DIM * DIM;
    int i = blockIdx.x * 256 + threadIdx.x;
    float v;
    uint32_t* out;
    int j;
    if (i < nx)                  { v = x[i];            out = g_xt;  j = i; }
    else if (i < nx + NWQ)       { j = i - nx;       v = wq[j]; out = g_wqt; }
    else if (i < nx + NWQ + NWP) { j = i - nx - NWQ; v = wp[j]; out = g_wpt; }
    else return;
    out[sig16(j)] = tf32r(v);
}

// ---------------------------------------------------------------------------
// TF32 GEMM, 128 threads, CTA tile 128(M) x 64(N), warp tile 32x64,
// K chunk 32, 3-stage cp.async pipeline, single barrier per chunk.
// ---------------------------------------------------------------------------
#define GSTG2 24576
#define GEMM_SMEM (3 * GSTG2)
#define NCHUNK (KTOT / 32)
#define QSCALE (0.125f * 1.4426950408889634f)

template<int MODE>
__global__ __launch_bounds__(128, 3)
void gemm_tc(float* __restrict__ C, int M, int NC,
             const int* __restrict__ Hp, const int* __restrict__ Wp)
{
    extern __shared__ __align__(16) char dsm[];
    const uint32_t smb = smem_u32(dsm);

    const int tid = threadIdx.x;
    const int wid = tid >> 5;
    const int lane = tid & 31;
    const int gID = lane >> 2, cA = lane & 3;

    const int m0 = blockIdx.y * 128;
    const int n0 = blockIdx.x * 64;

    const uint32_t* A = MODE ? g_at : g_xt;
    const uint32_t* B = MODE ? g_wpt : g_wqt;

    auto issue = [&](int stg, int chunk) {
        const uint32_t sb = smb + stg * GSTG2;
        const int k0 = chunk * 32;
#pragma unroll
        for (int t = 0; t < 8; t++) {            // A: 128 rows x 8 units
            int idx = t * 128 + tid;
            int row = idx >> 3, u = idx & 7;
            uint32_t so = (uint32_t)row * 128 + ((u + 4 * row) & 7) * 16;
            cpa16(sb + so, A + (size_t)(m0 + row) * KTOT + k0 + u * 4);
        }
#pragma unroll
        for (int t = 0; t < 4; t++) {            // B: 64 rows x 8 units
            int idx = t * 128 + tid;
            int row = idx >> 3, u = idx & 7;
            uint32_t so = (uint32_t)row * 128 + ((u + 4 * row) & 7) * 16;
            cpa16(sb + 16384 + so, B + (size_t)(n0 + row) * KTOT + k0 + u * 4);
        }
        CPA_COMMIT();
    };

    float acc[2][8][4];
#pragma unroll
    for (int i = 0; i < 2; i++)
#pragma unroll
        for (int j = 0; j < 8; j++)
#pragma unroll
            for (int k = 0; k < 4; k++) acc[i][j][k] = 0.f;

    issue(0, 0);
    issue(1, 1);

    for (int chunk = 0; chunk < NCHUNK; chunk++) {
        if (chunk + 1 < NCHUNK) CPA_WAIT1(); else CPA_WAIT0();
        __syncthreads();        // publishes stage data + proves prior reads done
        if (chunk + 2 < NCHUNK) issue((chunk + 2) % 3, chunk + 2);

        const char* aC = dsm + (chunk % 3) * GSTG2;
        const char* bC = aC + 16384;

#pragma unroll
        for (int g = 0; g < 2; g++) {
            uint4 alo[2], ahi[2];
#pragma unroll
            for (int mt = 0; mt < 2; mt++) {
                int rA = wid * 32 + mt * 16 + gID;
                uint32_t u = (uint32_t)((g * 4 + cA + 4 * rA) & 7) * 16;
                alo[mt] = *(const uint4*)(aC + rA * 128 + u);
                ahi[mt] = *(const uint4*)(aC + (rA + 8) * 128 + u);
            }
#pragma unroll
            for (int ng = 0; ng < 8; ng++) {
                int rB = ng * 8 + gID;
                uint32_t u = (uint32_t)((g * 4 + cA + 4 * rB) & 7) * 16;
                uint4 bb = *(const uint4*)(bC + rB * 128 + u);
#pragma unroll
                for (int mt = 0; mt < 2; mt++) {
                    mmatf(acc[mt][ng], alo[mt].x, ahi[mt].x, alo[mt].y, ahi[mt].y,
                          bb.x, bb.y);
                    mmatf(acc[mt][ng], alo[mt].z, ahi[mt].z, alo[mt].w, ahi[mt].w,
                          bb.z, bb.w);
                }
            }
        }
    }

    // ---------------- epilogue ----------------
    int Nseq = 0;
    if (MODE == 0) Nseq = (*Wp) * (*Hp);

#pragma unroll
    for (int mt = 0; mt < 2; mt++) {
#pragma unroll
        for (int ro = 0; ro < 2; ro++) {
            const int m = m0 + wid * 32 + mt * 16 + ro * 8 + gID;
            int b = 0, n = 0;
            if (MODE == 0) { b = m / Nseq; n = m - b * Nseq; }
#pragma unroll
            for (int nt = 0; nt < 8; nt++) {
                const int d = n0 + nt * 8 + cA * 2;
                float a0 = acc[mt][nt][ro * 2 + 0];
                float a1 = acc[mt][nt][ro * 2 + 1];
                if (MODE == 0) {
                    const int which = d >> 9;
                    const int h = (d >> 6) & 7;
                    const int e = d & 63;
                    size_t off = ((size_t)(b * NH + h) * Nseq + n) * HD;
                    if (which == 0) {
                        g_qt[off + sig16(e)]     = tf32r(a0 * QSCALE);
                        g_qt[off + sig16(e + 1)] = tf32r(a1 * QSCALE);
                    } else if (which == 1) {
                        g_kt[off + sig16(e)]     = tf32r(a0);
                        g_kt[off + sig16(e + 1)] = tf32r(a1);
                    } else {
                        uint32_t uh, ul;
                        split2(a0, a1, uh, ul);
                        *(uint32_t*)(g_vhi + off + e) = uh;
                        *(uint32_t*)(g_vlo + off + e) = ul;
                    }
                } else {
                    *(float2*)(C + (size_t)m * NC + d) = make_float2(a0, a1);
                }
            }
        }
    }
}

// ---------------------------------------------------------------------------
// Flash attention, 128 threads, 64 Q rows per CTA (4 warps x 16 rows).
// S = Q K^T tf32 (log2e pre-scaled); factorized decay bias (W==32 fast path);
// P -> bf16 hi/lo; O += P V bf16 3-term. 2-stage cp.async K/V pipeline,
// single barrier per tile.
// ---------------------------------------------------------------------------
#define VHOFF 16384
#define VLOFF 25600
#define ASTG2 34816
#define ASTR 72
#define ATTN_SMEM (2 * ASTG2 + 256 + 512 + 512)

__global__ __launch_bounds__(128, 3)
void attn_mma(const float* __restrict__ log_decay, int M,
              const int* __restrict__ Hp, const int* __restrict__ Wp)
{
    extern __shared__ __align__(16) char sm[];
    const uint32_t smb = smem_u32(sm);
    float* Ts  = (float*)(sm + 2 * ASTG2);
    int*   krs = (int*)(sm + 2 * ASTG2 + 256);
    int*   kcs = (int*)(sm + 2 * ASTG2 + 768);

    const int Wv = *Wp, Hv = *Hp;
    const int Nseq = Wv * Hv;
    const int ntiles = Nseq / 64;
    const bool fast = (Wv == 32);
    const int h = blockIdx.y;
    const int m0 = blockIdx.x * 64;
    const int b = m0 / Nseq;
    const int n0 = m0 - b * Nseq;

    const int tid = threadIdx.x, w = tid >> 5, lane = tid & 31;
    const int gID = lane >> 2, cA = lane & 3, t2 = cA * 2;

    const float decay = log1pf(__expf(log_decay[h]));
    if (tid < 64) Ts[tid] = __expf(-decay * (float)tid);

    const size_t bh_off = (size_t)(b * NH + h) * Nseq * HD;
    const uint32_t* Qt_g = g_qt + bh_off + (size_t)n0 * HD;
    const uint32_t* Kt_g = g_kt + bh_off;
    const __nv_bfloat16* Vh_g = g_vhi + bh_off;
    const __nv_bfloat16* Vl_g = g_vlo + bh_off;

    const int nr0 = n0 + w * 16 + gID;
    const int qr0 = nr0 / Wv, qc0 = nr0 - qr0 * Wv;
    const int nr1 = nr0 + 8;
    const int qr1 = nr1 / Wv, qc1 = nr1 - qr1 * Wv;

    // ---- stage Q (64 rows x 16 units, swizzled; aliases stage-0 K) ----
#pragma unroll
    for (int i = 0; i < 8; i++) {
        int idx = i * 128 + tid;
        int row = idx >> 4, u = idx & 15;
        cpa16(smb + (uint32_t)row * 256 + ((u + 4 * row) & 15) * 16,
              Qt_g + (size_t)row * HD + u * 4);
    }
    CPA_COMMIT();
    CPA_WAIT0();
    __syncthreads();

    // ---- Q fragments (persistent, tf32) ----
    uint4 qlo[4], qhi[4];
    {
        const int r0 = w * 16 + gID;
#pragma unroll
        for (int g = 0; g < 4; g++) {
            uint32_t u = (uint32_t)((g * 4 + cA + 4 * r0) & 15) * 16;
            qlo[g] = *(const uint4*)(sm + r0 * 256 + u);
            qhi[g] = *(const uint4*)(sm + (r0 + 8) * 256 + u);
        }
    }

    // ---- per-thread column decay factors (fixed across tiles, W==32) ----
    float tc0[8], tc1[8];
#pragma unroll
    for (int j = 0; j < 8; j++) {
        int kcol = (j >> 1) * 8 + t2 + (j & 1);
        tc0[j] = Ts[abs(qc0 - kcol)];
        tc1[j] = Ts[abs(qc1 - kcol)];
    }
    __syncthreads();   // Q frag / Ts reads done before stage-0 overwrite

    auto issue_kv = [&](int stg, int t0) {
        const uint32_t sb = smb + stg * ASTG2;
#pragma unroll
        for (int i = 0; i < 8; i++) {            // K: 64 rows x 16 units
            int idx = i * 128 + tid;
            int row = idx >> 4, u = idx & 15;
            cpa16(sb + (uint32_t)row * 256 + ((u + 4 * row) & 15) * 16,
                  Kt_g + (size_t)(t0 + row) * HD + u * 4);
        }
#pragma unroll
        for (int i = 0; i < 4; i++) {            // V hi/lo: 64 rows x 8 units
            int idx = i * 128 + tid;
            int row = idx >> 3, c8 = idx & 7;
            uint32_t so = (uint32_t)row * 144 + c8 * 16;
            size_t go = (size_t)(t0 + row) * HD + c8 * 8;
            cpa16(sb + VHOFF + so, Vh_g + go);
            cpa16(sb + VLOFF + so, Vl_g + go);
        }
        if (!fast && tid < 64) {
            int kn = t0 + tid;
            int kr = kn / Wv;
            krs[stg * 64 + tid] = kr;
            kcs[stg * 64 + tid] = kn - kr * Wv;
        }
        CPA_COMMIT();
    };

    float o[8][4];
#pragma unroll
    for (int i = 0; i < 8; i++)
#pragma unroll
        for (int j = 0; j < 4; j++) o[i][j] = 0.f;
    float lsum0 = 0.f, lsum1 = 0.f;

    const uint32_t vrow_l = (lane & 7) + ((lane >> 3) & 1) * 8;
    const uint32_t vcol_l = (lane >> 4) * 8;

    issue_kv(0, 0);

    for (int it = 0; it < ntiles; it++) {
        const int t0 = it * 64;
        CPA_WAIT0();
        __syncthreads();        // publishes stage it + proves stage (it+1)&1 reads done
        if (it + 1 < ntiles) issue_kv((it + 1) & 1, t0 + 64);

        const uint32_t sb = smb + (it & 1) * ASTG2;
        const char* sbc = sm + (it & 1) * ASTG2;

        // ---- S = Q K^T (tf32, scores pre-scaled by log2e) ----
        float s[8][4];
#pragma unroll
        for (int i = 0; i < 8; i++)
#pragma unroll
            for (int j = 0; j < 4; j++) s[i][j] = 0.f;

#pragma unroll
        for (int g = 0; g < 4; g++) {
#pragma unroll
            for (int ng = 0; ng < 8; ng++) {
                int rb = ng * 8 + gID;
                uint32_t u = (uint32_t)((g * 4 + cA + 4 * rb) & 15) * 16;
                uint4 kb = *(const uint4*)(sbc + rb * 256 + u);
                mmatf(s[ng], qlo[g].x, qhi[g].x, qlo[g].y, qhi[g].y, kb.x, kb.y);
                mmatf(s[ng], qlo[g].z, qhi[g].z, qlo[g].w, qhi[g].w, kb.z, kb.w);
            }
        }

        // ---- bias + exp + bf16 split pack ----
        uint32_t phi2[16], plo2[16];
        if (fast) {
            const int r0 = t0 >> 5;
            const float tr00 = Ts[abs(qr0 - r0)], tr01 = Ts[abs(qr0 - r0 - 1)];
            const float tr10 = Ts[abs(qr1 - r0)], tr11 = Ts[abs(qr1 - r0 - 1)];
#pragma unroll
            for (int nt = 0; nt < 8; nt++) {
                const int jj = (nt & 3) * 2;
                const float f0 = (nt < 4) ? tr00 : tr01;
                const float f1 = (nt < 4) ? tr10 : tr11;
                float p00 = ex2f(s[nt][0]) * (tc0[jj]     * f0);
                float p01 = ex2f(s[nt][1]) * (tc0[jj + 1] * f0);
                float p10 = ex2f(s[nt][2]) * (tc1[jj]     * f1);
                float p11 = ex2f(s[nt][3]) * (tc1[jj + 1] * f1);
                lsum0 += p00 + p01;
                lsum1 += p10 + p11;
                split2(p00, p01, phi2[nt * 2 + 0], plo2[nt * 2 + 0]);
                split2(p10, p11, phi2[nt * 2 + 1], plo2[nt * 2 + 1]);
            }
        } else {
            const int* kr_t = krs + (it & 1) * 64;
            const int* kc_t = kcs + (it & 1) * 64;
#pragma unroll
            for (int nt = 0; nt < 8; nt++) {
                const int c0 = nt * 8 + t2, c1 = c0 + 1;
                const int kr0 = kr_t[c0], kc0 = kc_t[c0];
                const int kr1 = kr_t[c1], kc1 = kc_t[c1];
                float p00 = ex2f(s[nt][0]) * Ts[abs(qr0 - kr0) + abs(qc0 - kc0)];
                float p01 = ex2f(s[nt][1]) * Ts[abs(qr0 - kr1) + abs(qc0 - kc1)];
                float p10 = ex2f(s[nt][2]) * Ts[abs(qr1 - kr0) + abs(qc1 - kc0)];
                float p11 = ex2f(s[nt][3]) * Ts[abs(qr1 - kr1) + abs(qc1 - kc1)];
                lsum0 += p00 + p01;
                lsum1 += p10 + p11;
                split2(p00, p01, phi2[nt * 2 + 0], plo2[nt * 2 + 0]);
                split2(p10, p11, phi2[nt * 2 + 1], plo2[nt * 2 + 1]);
            }
        }

        // ---- O += P V (bf16 3-term) ----
#pragma unroll
        for (int g = 0; g < 4; g++) {
            const uint32_t* pah = &phi2[4 * g];
            const uint32_t* pal = &plo2[4 * g];
#pragma unroll
            for (int ntp = 0; ntp < 4; ntp++) {
                uint32_t off = ((16u * g + vrow_l) * ASTR + 16 * ntp + vcol_l) * 2;
                uint32_t vbh[4], vbl[4];
                ldsm4t(vbh, sb + VHOFF + off);
                ldsm4t(vbl, sb + VLOFF + off);
                mma16816(o[2 * ntp],     pah, vbh);
                mma16816(o[2 * ntp],     pah, vbl);
                mma16816(o[2 * ntp],     pal, vbh);
                mma16816(o[2 * ntp + 1], pah, vbh + 2);
                mma16816(o[2 * ntp + 1], pah, vbl + 2);
                mma16816(o[2 * ntp + 1], pal, vbh + 2);
            }
        }
    }

    // ---- normalize + write tf32 sigma-perm ----
    lsum0 += __shfl_xor_sync(0xFFFFFFFFu, lsum0, 1);
    lsum0 += __shfl_xor_sync(0xFFFFFFFFu, lsum0, 2);
    lsum1 += __shfl_xor_sync(0xFFFFFFFFu, lsum1, 1);
    lsum1 += __shfl_xor_sync(0xFFFFFFFFu, lsum1, 2);
    const float inv0 = 1.f / lsum0, inv1 = 1.f / lsum1;

    const size_t rb0 = (size_t)(m0 + w * 16 + gID) * DIM;
    const size_t rb1 = rb0 + 8 * DIM;
#pragma unroll
    for (int nt = 0; nt < 8; nt++) {
        const int col = h * HD + nt * 8 + t2;
        g_at[rb0 + sig16(col)]     = tf32r(o[nt][0] * inv0);
        g_at[rb0 + sig16(col + 1)] = tf32r(o[nt][1] * inv0);
        g_at[rb1 + sig16(col)]     = tf32r(o[nt][2] * inv1);
        g_at[rb1 + sig16(col + 1)] = tf32r(o[nt][3] * inv1);
    }
}

// ---------------------------------------------------------------------------
extern "C" void kernel_launch(void* const* d_in, const int* in_sizes, int n_in,
                              void* d_out, int out_size)
{
    const float* x      = (const float*)d_in[0];
    const float* w_qkv  = (const float*)d_in[1];
    const float* w_proj = (const float*)d_in[2];
    const float* ldec   = (const float*)d_in[3];
    const int* Hp = (const int*)d_in[4];
    const int* Wp = (const int*)d_in[5];

    const int M = in_sizes[0] / DIM;

    cudaFuncSetAttribute(gemm_tc<0>, cudaFuncAttributeMaxDynamicSharedMemorySize, GEMM_SMEM);
    cudaFuncSetAttribute(gemm_tc<1>, cudaFuncAttributeMaxDynamicSharedMemorySize, GEMM_SMEM);
    cudaFuncSetAttribute(attn_mma,   cudaFuncAttributeMaxDynamicSharedMemorySize, ATTN_SMEM);

    // 0) fp32 -> tf32 (sigma-permuted)
    {
        int total = M * DIM + 3 * DIM * DIM + DIM * DIM;
        prep<<<(total + 255) / 256, 256>>>(x, w_qkv, w_proj, M * DIM);
    }
    // 1) QKV projection (tf32) -> split q/k/v head-major
    gemm_tc<0><<<dim3(3 * DIM / 64, M / 128), 128, GEMM_SMEM>>>(nullptr, M, 3 * DIM, Hp, Wp);
    // 2) spatial-decay flash attention
    attn_mma<<<dim3(M / 64, NH), 128, ATTN_SMEM>>>(ldec, M, Hp, Wp);
    // 3) output projection (tf32)
    gemm_tc<1><<<dim3(DIM / 64, M / 128), 128, GEMM_SMEM>>>((float*)d_out, M, DIM,
                                                            nullptr, nullptr);
}

// round 14
// speedup vs baseline: 1.1899x; 1.0125x over previous
#include <cuda_runtime.h>
#include <cuda_bf16.h>
#include <cstdint>

#define DIM 512
#define NH 8
#define HD 64
#define MAXM 8192
#define KTOT 512

// ---------------------------------------------------------------------------
// Scratch (allocation-free rule: __device__ globals)
// ---------------------------------------------------------------------------
__device__ uint32_t g_xt[MAXM * DIM];
__device__ uint32_t g_wqt[3 * DIM * DIM];
__device__ uint32_t g_wpt[DIM * DIM];
__device__ uint32_t g_qt[MAXM * DIM];            // q head-major, x hd^-.5*log2e
__device__ uint32_t g_kt[MAXM * DIM];
__device__ __nv_bfloat16 g_vhi[MAXM * DIM], g_vlo[MAXM * DIM];
__device__ uint32_t g_at[MAXM * DIM];            // attn out, tf32, sigma-perm

// ---------------------------------------------------------------------------
// helpers (compute_103-safe: sm_80 baseline PTX)
// ---------------------------------------------------------------------------
__device__ __forceinline__ uint32_t smem_u32(const void* p) {
    uint32_t a;
    asm("{ .reg .u64 t; cvta.to.shared.u64 t, %1; cvt.u32.u64 %0, t; }"
        : "=r"(a) : "l"(p));
    return a;
}
__device__ __forceinline__ uint32_t tf32r(float v) {
    uint32_t r;
    asm("cvt.rna.tf32.f32 %0, %1;" : "=r"(r) : "f"(v));
    return r;
}
__device__ __forceinline__ float ex2f(float x) {
    float r;
    asm("ex2.approx.f32 %0, %1;" : "=f"(r) : "f"(x));
    return r;
}
__device__ __forceinline__ int sig16(int k) {
    return (k & ~15) | (((k & 3) << 2) | ((k >> 2) & 3));
}
__device__ __forceinline__ void mmatf(float* c, uint32_t a0, uint32_t a1,
                                      uint32_t a2, uint32_t a3,
                                      uint32_t b0, uint32_t b1) {
    asm volatile(
        "mma.sync.aligned.m16n8k8.row.col.f32.tf32.tf32.f32 "
        "{%0,%1,%2,%3}, {%4,%5,%6,%7}, {%8,%9}, {%0,%1,%2,%3};"
        : "+f"(c[0]), "+f"(c[1]), "+f"(c[2]), "+f"(c[3])
        : "r"(a0), "r"(a1), "r"(a2), "r"(a3), "r"(b0), "r"(b1));
}
__device__ __forceinline__ void ldsm4t(uint32_t* r, uint32_t addr) {
    asm volatile("ldmatrix.sync.aligned.m8n8.x4.trans.shared.b16 {%0,%1,%2,%3}, [%4];"
                 : "=r"(r[0]), "=r"(r[1]), "=r"(r[2]), "=r"(r[3]) : "r"(addr));
}
__device__ __forceinline__ void mma16816(float* c, const uint32_t* a,
                                         const uint32_t* b) {
    asm volatile(
        "mma.sync.aligned.m16n8k16.row.col.f32.bf16.bf16.f32 "
        "{%0,%1,%2,%3}, {%4,%5,%6,%7}, {%8,%9}, {%0,%1,%2,%3};"
        : "+f"(c[0]), "+f"(c[1]), "+f"(c[2]), "+f"(c[3])
        : "r"(a[0]), "r"(a[1]), "r"(a[2]), "r"(a[3]), "r"(b[0]), "r"(b[1]));
}
__device__ __forceinline__ void split2(float a, float b, uint32_t& uhi, uint32_t& ulo) {
    __nv_bfloat162 hh = __floats2bfloat162_rn(a, b);
    __nv_bfloat162 ll = __floats2bfloat162_rn(a - __bfloat162float(hh.x),
                                              b - __bfloat162float(hh.y));
    uhi = *(uint32_t*)&hh;
    ulo = *(uint32_t*)&ll;
}
__device__ __forceinline__ void cpa16(uint32_t saddr, const void* g) {
    asm volatile("cp.async.cg.shared.global [%0], [%1], 16;"
                 :: "r"(saddr), "l"(g) : "memory");
}
#define CPA_COMMIT() asm volatile("cp.async.commit_group;" ::: "memory")
#define CPA_WAIT1()  asm volatile("cp.async.wait_group 1;" ::: "memory")
#define CPA_WAIT0()  asm volatile("cp.async.wait_group 0;" ::: "memory")

// ---------------------------------------------------------------------------
// Prep: fp32 -> tf32 (rna), sigma-permuted. One thread per 16-element block:
// sigma within a 16-block is a 4x4 transpose -> 4x LDG.128 + 4x STG.128.
// ---------------------------------------------------------------------------
__global__ void prep(const float* __restrict__ x, const float* __restrict__ wq,
                     const float* __restrict__ wp, int nx) {
    const int NWQ = 3 * DIM * DIM, NWP = DIM * DIM;
    int i = (blockIdx.x * 256 + threadIdx.x) * 16;   // block base (segments are 16-aligned)
    const float* src;
    uint32_t* out;
    int j;
    if (i < nx)                  { src = x;  out = g_xt;  j = i; }
    else if (i < nx + NWQ)       { j = i - nx;       src = wq; out = g_wqt; }
    else if (i < nx + NWQ + NWP) { j = i - nx - NWQ; src = wp; out = g_wpt; }
    else return;

    float4 r0 = *(const float4*)(src + j);
    float4 r1 = *(const float4*)(src + j + 4);
    float4 r2 = *(const float4*)(src + j + 8);
    float4 r3 = *(const float4*)(src + j + 12);
    // out[j + ((b<<2)|a)] = tf32(in[j + 4a + b])  ->  out quad p = {r0[p],r1[p],r2[p],r3[p]}
    uint4 o;
    o.x = tf32r(r0.x); o.y = tf32r(r1.x); o.z = tf32r(r2.x); o.w = tf32r(r3.x);
    *(uint4*)(out + j)      = o;
    o.x = tf32r(r0.y); o.y = tf32r(r1.y); o.z = tf32r(r2.y); o.w = tf32r(r3.y);
    *(uint4*)(out + j + 4)  = o;
    o.x = tf32r(r0.z); o.y = tf32r(r1.z); o.z = tf32r(r2.z); o.w = tf32r(r3.z);
    *(uint4*)(out + j + 8)  = o;
    o.x = tf32r(r0.w); o.y = tf32r(r1.w); o.z = tf32r(r2.w); o.w = tf32r(r3.w);
    *(uint4*)(out + j + 12) = o;
}

// ---------------------------------------------------------------------------
// TF32 GEMM, 128 threads, CTA tile 128(M) x 64(N), warp tile 32x64,
// K chunk 32, 2-stage cp.async pipeline (R8 structure, measured best).
// ---------------------------------------------------------------------------
#define GSTG2 24576
#define GEMM_SMEM (2 * GSTG2)
#define NCHUNK (KTOT / 32)
#define QSCALE (0.125f * 1.4426950408889634f)

template<int MODE>
__global__ __launch_bounds__(128, 3)
void gemm_tc(float* __restrict__ C, int M, int NC,
             const int* __restrict__ Hp, const int* __restrict__ Wp)
{
    extern __shared__ __align__(16) char dsm[];
    const uint32_t smb = smem_u32(dsm);

    const int tid = threadIdx.x;
    const int wid = tid >> 5;
    const int lane = tid & 31;
    const int gID = lane >> 2, cA = lane & 3;

    const int m0 = blockIdx.y * 128;
    const int n0 = blockIdx.x * 64;

    const uint32_t* A = MODE ? g_at : g_xt;
    const uint32_t* B = MODE ? g_wpt : g_wqt;

    auto issue = [&](int stg, int chunk) {
        const uint32_t sb = smb + stg * GSTG2;
        const int k0 = chunk * 32;
#pragma unroll
        for (int t = 0; t < 8; t++) {            // A: 128 rows x 8 units
            int idx = t * 128 + tid;
            int row = idx >> 3, u = idx & 7;
            uint32_t so = (uint32_t)row * 128 + ((u + 4 * row) & 7) * 16;
            cpa16(sb + so, A + (size_t)(m0 + row) * KTOT + k0 + u * 4);
        }
#pragma unroll
        for (int t = 0; t < 4; t++) {            // B: 64 rows x 8 units
            int idx = t * 128 + tid;
            int row = idx >> 3, u = idx & 7;
            uint32_t so = (uint32_t)row * 128 + ((u + 4 * row) & 7) * 16;
            cpa16(sb + 16384 + so, B + (size_t)(n0 + row) * KTOT + k0 + u * 4);
        }
        CPA_COMMIT();
    };

    float acc[2][8][4];
#pragma unroll
    for (int i = 0; i < 2; i++)
#pragma unroll
        for (int j = 0; j < 8; j++)
#pragma unroll
            for (int k = 0; k < 4; k++) acc[i][j][k] = 0.f;

    issue(0, 0);

    for (int chunk = 0; chunk < NCHUNK; chunk++) {
        if (chunk + 1 < NCHUNK) { issue((chunk + 1) & 1, chunk + 1); CPA_WAIT1(); }
        else                    { CPA_WAIT0(); }
        __syncthreads();

        const char* aC = dsm + (chunk & 1) * GSTG2;
        const char* bC = aC + 16384;

#pragma unroll
        for (int g = 0; g < 2; g++) {
            uint4 alo[2], ahi[2];
#pragma unroll
            for (int mt = 0; mt < 2; mt++) {
                int rA = wid * 32 + mt * 16 + gID;
                uint32_t u = (uint32_t)((g * 4 + cA + 4 * rA) & 7) * 16;
                alo[mt] = *(const uint4*)(aC + rA * 128 + u);
                ahi[mt] = *(const uint4*)(aC + (rA + 8) * 128 + u);
            }
#pragma unroll
            for (int ng = 0; ng < 8; ng++) {
                int rB = ng * 8 + gID;
                uint32_t u = (uint32_t)((g * 4 + cA + 4 * rB) & 7) * 16;
                uint4 bb = *(const uint4*)(bC + rB * 128 + u);
#pragma unroll
                for (int mt = 0; mt < 2; mt++) {
                    mmatf(acc[mt][ng], alo[mt].x, ahi[mt].x, alo[mt].y, ahi[mt].y,
                          bb.x, bb.y);
                    mmatf(acc[mt][ng], alo[mt].z, ahi[mt].z, alo[mt].w, ahi[mt].w,
                          bb.z, bb.w);
                }
            }
        }
        __syncthreads();
    }

    // ---------------- epilogue ----------------
    int Nseq = 0;
    if (MODE == 0) Nseq = (*Wp) * (*Hp);

#pragma unroll
    for (int mt = 0; mt < 2; mt++) {
#pragma unroll
        for (int ro = 0; ro < 2; ro++) {
            const int m = m0 + wid * 32 + mt * 16 + ro * 8 + gID;
            int b = 0, n = 0;
            if (MODE == 0) { b = m / Nseq; n = m - b * Nseq; }
#pragma unroll
            for (int nt = 0; nt < 8; nt++) {
                const int d = n0 + nt * 8 + cA * 2;
                float a0 = acc[mt][nt][ro * 2 + 0];
                float a1 = acc[mt][nt][ro * 2 + 1];
                if (MODE == 0) {
                    const int which = d >> 9;
                    const int h = (d >> 6) & 7;
                    const int e = d & 63;
                    size_t off = ((size_t)(b * NH + h) * Nseq + n) * HD;
                    if (which == 0) {
                        g_qt[off + sig16(e)]     = tf32r(a0 * QSCALE);
                        g_qt[off + sig16(e + 1)] = tf32r(a1 * QSCALE);
                    } else if (which == 1) {
                        g_kt[off + sig16(e)]     = tf32r(a0);
                        g_kt[off + sig16(e + 1)] = tf32r(a1);
                    } else {
                        uint32_t uh, ul;
                        split2(a0, a1, uh, ul);
                        *(uint32_t*)(g_vhi + off + e) = uh;
                        *(uint32_t*)(g_vlo + off + e) = ul;
                    }
                } else {
                    *(float2*)(C + (size_t)m * NC + d) = make_float2(a0, a1);
                }
            }
        }
    }
}

// ---------------------------------------------------------------------------
// Flash attention, 128 threads, 64 Q rows per CTA (4 warps x 16 rows).
// S = Q K^T tf32 (log2e pre-scaled); factorized decay bias (W==32 fast path);
// P split bf16 hi/lo (3-term PV: Ph*Vh + Ph*Vl + Pl*Vh) with pack fused
// per key-group (8 live P regs instead of 32). 2-stage cp.async pipeline.
// ---------------------------------------------------------------------------
#define VHOFF 16384
#define VLOFF 25600
#define ASTG2 34816
#define ASTR 72
#define ATTN_SMEM (2 * ASTG2 + 256 + 512 + 512)

__global__ __launch_bounds__(128, 3)
void attn_mma(const float* __restrict__ log_decay, int M,
              const int* __restrict__ Hp, const int* __restrict__ Wp)
{
    extern __shared__ __align__(16) char sm[];
    const uint32_t smb = smem_u32(sm);
    float* Ts  = (float*)(sm + 2 * ASTG2);
    int*   krs = (int*)(sm + 2 * ASTG2 + 256);
    int*   kcs = (int*)(sm + 2 * ASTG2 + 768);

    const int Wv = *Wp, Hv = *Hp;
    const int Nseq = Wv * Hv;
    const int ntiles = Nseq / 64;
    const bool fast = (Wv == 32);
    const int h = blockIdx.y;
    const int m0 = blockIdx.x * 64;
    const int b = m0 / Nseq;
    const int n0 = m0 - b * Nseq;

    const int tid = threadIdx.x, w = tid >> 5, lane = tid & 31;
    const int gID = lane >> 2, cA = lane & 3, t2 = cA * 2;

    const float decay = log1pf(__expf(log_decay[h]));
    if (tid < 64) Ts[tid] = __expf(-decay * (float)tid);

    const size_t bh_off = (size_t)(b * NH + h) * Nseq * HD;
    const uint32_t* Qt_g = g_qt + bh_off + (size_t)n0 * HD;
    const uint32_t* Kt_g = g_kt + bh_off;
    const __nv_bfloat16* Vh_g = g_vhi + bh_off;
    const __nv_bfloat16* Vl_g = g_vlo + bh_off;

    const int nr0 = n0 + w * 16 + gID;
    const int qr0 = nr0 / Wv, qc0 = nr0 - qr0 * Wv;
    const int nr1 = nr0 + 8;
    const int qr1 = nr1 / Wv, qc1 = nr1 - qr1 * Wv;

    // ---- stage Q (64 rows x 16 units, swizzled; aliases stage-0 K) ----
#pragma unroll
    for (int i = 0; i < 8; i++) {
        int idx = i * 128 + tid;
        int row = idx >> 4, u = idx & 15;
        cpa16(smb + (uint32_t)row * 256 + ((u + 4 * row) & 15) * 16,
              Qt_g + (size_t)row * HD + u * 4);
    }
    CPA_COMMIT();
    CPA_WAIT0();
    __syncthreads();

    // ---- Q fragments (persistent, tf32) ----
    uint4 qlo[4], qhi[4];
    {
        const int r0 = w * 16 + gID;
#pragma unroll
        for (int g = 0; g < 4; g++) {
            uint32_t u = (uint32_t)((g * 4 + cA + 4 * r0) & 15) * 16;
            qlo[g] = *(const uint4*)(sm + r0 * 256 + u);
            qhi[g] = *(const uint4*)(sm + (r0 + 8) * 256 + u);
        }
    }

    // ---- per-thread column decay factors (fixed across tiles, W==32) ----
    float tc0[8], tc1[8];
#pragma unroll
    for (int j = 0; j < 8; j++) {
        int kcol = (j >> 1) * 8 + t2 + (j & 1);
        tc0[j] = Ts[abs(qc0 - kcol)];
        tc1[j] = Ts[abs(qc1 - kcol)];
    }
    __syncthreads();   // Q frag / Ts reads done before stage-0 overwrite

    auto issue_kv = [&](int stg, int t0) {
        const uint32_t sb = smb + stg * ASTG2;
#pragma unroll
        for (int i = 0; i < 8; i++) {            // K: 64 rows x 16 units
            int idx = i * 128 + tid;
            int row = idx >> 4, u = idx & 15;
            cpa16(sb + (uint32_t)row * 256 + ((u + 4 * row) & 15) * 16,
                  Kt_g + (size_t)(t0 + row) * HD + u * 4);
        }
#pragma unroll
        for (int i = 0; i < 4; i++) {            // V hi/lo: 64 rows x 8 units
            int idx = i * 128 + tid;
            int row = idx >> 3, c8 = idx & 7;
            uint32_t so = (uint32_t)row * 144 + c8 * 16;
            size_t go = (size_t)(t0 + row) * HD + c8 * 8;
            cpa16(sb + VHOFF + so, Vh_g + go);
            cpa16(sb + VLOFF + so, Vl_g + go);
        }
        if (!fast && tid < 64) {
            int kn = t0 + tid;
            int kr = kn / Wv;
            krs[stg * 64 + tid] = kr;
            kcs[stg * 64 + tid] = kn - kr * Wv;
        }
        CPA_COMMIT();
    };

    float o[8][4];
#pragma unroll
    for (int i = 0; i < 8; i++)
#pragma unroll
        for (int j = 0; j < 4; j++) o[i][j] = 0.f;
    float lsum0 = 0.f, lsum1 = 0.f;

    const uint32_t vrow_l = (lane & 7) + ((lane >> 3) & 1) * 8;
    const uint32_t vcol_l = (lane >> 4) * 8;

    issue_kv(0, 0);

    for (int it = 0; it < ntiles; it++) {
        const int t0 = it * 64;
        if (it + 1 < ntiles) { issue_kv((it + 1) & 1, t0 + 64); CPA_WAIT1(); }
        else                 { CPA_WAIT0(); }
        __syncthreads();

        const uint32_t sb = smb + (it & 1) * ASTG2;
        const char* sbc = sm + (it & 1) * ASTG2;

        // ---- S = Q K^T (tf32, scores pre-scaled by log2e) ----
        float s[8][4];
#pragma unroll
        for (int i = 0; i < 8; i++)
#pragma unroll
            for (int j = 0; j < 4; j++) s[i][j] = 0.f;

#pragma unroll
        for (int g = 0; g < 4; g++) {
#pragma unroll
            for (int ng = 0; ng < 8; ng++) {
                int rb = ng * 8 + gID;
                uint32_t u = (uint32_t)((g * 4 + cA + 4 * rb) & 15) * 16;
                uint4 kb = *(const uint4*)(sbc + rb * 256 + u);
                mmatf(s[ng], qlo[g].x, qhi[g].x, qlo[g].y, qhi[g].y, kb.x, kb.y);
                mmatf(s[ng], qlo[g].z, qhi[g].z, qlo[g].w, qhi[g].w, kb.z, kb.w);
            }
        }

        // ---- per key-group: bias + exp + split pack, then 3-term PV ----
        const int r0 = t0 >> 5;
        float tr00 = 0.f, tr01 = 0.f, tr10 = 0.f, tr11 = 0.f;
        if (fast) {
            tr00 = Ts[abs(qr0 - r0)]; tr01 = Ts[abs(qr0 - r0 - 1)];
            tr10 = Ts[abs(qr1 - r0)]; tr11 = Ts[abs(qr1 - r0 - 1)];
        }
        const int* kr_t = krs + (it & 1) * 64;
        const int* kc_t = kcs + (it & 1) * 64;

#pragma unroll
        for (int g = 0; g < 4; g++) {
            uint32_t ph[4], pl[4];
#pragma unroll
            for (int q = 0; q < 2; q++) {
                const int nt = 2 * g + q;
                float p00, p01, p10, p11;
                if (fast) {
                    const int jj = (nt & 3) * 2;
                    const float f0 = (nt < 4) ? tr00 : tr01;
                    const float f1 = (nt < 4) ? tr10 : tr11;
                    p00 = ex2f(s[nt][0]) * (tc0[jj]     * f0);
                    p01 = ex2f(s[nt][1]) * (tc0[jj + 1] * f0);
                    p10 = ex2f(s[nt][2]) * (tc1[jj]     * f1);
                    p11 = ex2f(s[nt][3]) * (tc1[jj + 1] * f1);
                } else {
                    const int c0 = nt * 8 + t2, c1 = c0 + 1;
                    const int kr0 = kr_t[c0], kc0 = kc_t[c0];
                    const int kr1 = kr_t[c1], kc1 = kc_t[c1];
                    p00 = ex2f(s[nt][0]) * Ts[abs(qr0 - kr0) + abs(qc0 - kc0)];
                    p01 = ex2f(s[nt][1]) * Ts[abs(qr0 - kr1) + abs(qc0 - kc1)];
                    p10 = ex2f(s[nt][2]) * Ts[abs(qr1 - kr0) + abs(qc1 - kc0)];
                    p11 = ex2f(s[nt][3]) * Ts[abs(qr1 - kr1) + abs(qc1 - kc1)];
                }
                lsum0 += p00 + p01;
                lsum1 += p10 + p11;
                split2(p00, p01, ph[q * 2 + 0], pl[q * 2 + 0]);
                split2(p10, p11, ph[q * 2 + 1], pl[q * 2 + 1]);
            }
#pragma unroll
            for (int ntp = 0; ntp < 4; ntp++) {
                uint32_t off = ((16u * g + vrow_l) * ASTR + 16 * ntp + vcol_l) * 2;
                uint32_t vbh[4], vbl[4];
                ldsm4t(vbh, sb + VHOFF + off);
                ldsm4t(vbl, sb + VLOFF + off);
                mma16816(o[2 * ntp],     ph, vbh);
                mma16816(o[2 * ntp],     ph, vbl);
                mma16816(o[2 * ntp],     pl, vbh);
                mma16816(o[2 * ntp + 1], ph, vbh + 2);
                mma16816(o[2 * ntp + 1], ph, vbl + 2);
                mma16816(o[2 * ntp + 1], pl, vbh + 2);
            }
        }
        __syncthreads();
    }

    // ---- normalize + write tf32 sigma-perm ----
    lsum0 += __shfl_xor_sync(0xFFFFFFFFu, lsum0, 1);
    lsum0 += __shfl_xor_sync(0xFFFFFFFFu, lsum0, 2);
    lsum1 += __shfl_xor_sync(0xFFFFFFFFu, lsum1, 1);
    lsum1 += __shfl_xor_sync(0xFFFFFFFFu, lsum1, 2);
    const float inv0 = 1.f / lsum0, inv1 = 1.f / lsum1;

    const size_t rb0 = (size_t)(m0 + w * 16 + gID) * DIM;
    const size_t rb1 = rb0 + 8 * DIM;
#pragma unroll
    for (int nt = 0; nt < 8; nt++) {
        const int col = h * HD + nt * 8 + t2;
        g_at[rb0 + sig16(col)]     = tf32r(o[nt][0] * inv0);
        g_at[rb0 + sig16(col + 1)] = tf32r(o[nt][1] * inv0);
        g_at[rb1 + sig16(col)]     = tf32r(o[nt][2] * inv1);
        g_at[rb1 + sig16(col + 1)] = tf32r(o[nt][3] * inv1);
    }
}

// ---------------------------------------------------------------------------
extern "C" void kernel_launch(void* const* d_in, const int* in_sizes, int n_in,
                              void* d_out, int out_size)
{
    const float* x      = (const float*)d_in[0];
    const float* w_qkv  = (const float*)d_in[1];
    const float* w_proj = (const float*)d_in[2];
    const float* ldec   = (const float*)d_in[3];
    const int* Hp = (const int*)d_in[4];
    const int* Wp = (const int*)d_in[5];

    const int M = in_sizes[0] / DIM;

    cudaFuncSetAttribute(gemm_tc<0>, cudaFuncAttributeMaxDynamicSharedMemorySize, GEMM_SMEM);
    cudaFuncSetAttribute(gemm_tc<1>, cudaFuncAttributeMaxDynamicSharedMemorySize, GEMM_SMEM);
    cudaFuncSetAttribute(attn_mma,   cudaFuncAttributeMaxDynamicSharedMemorySize, ATTN_SMEM);

    // 0) fp32 -> tf32 (sigma-permuted), 16 elems/thread (4x4 transpose blocks)
    {
        int total = M * DIM + 3 * DIM * DIM + DIM * DIM;
        int blocks = (total / 16 + 255) / 256;
        prep<<<blocks, 256>>>(x, w_qkv, w_proj, M * DIM);
    }
    // 1) QKV projection (tf32) -> split q/k/v head-major
    gemm_tc<0><<<dim3(3 * DIM / 64, M / 128), 128, GEMM_SMEM>>>(nullptr, M, 3 * DIM, Hp, Wp);
    // 2) spatial-decay flash attention
    attn_mma<<<dim3(M / 64, NH), 128, ATTN_SMEM>>>(ldec, M, Hp, Wp);
    // 3) output projection (tf32)
    gemm_tc<1><<<dim3(DIM / 64, M / 128), 128, GEMM_SMEM>>>((float*)d_out, M, DIM,
                                                            nullptr, nullptr);
}

// round 15
// speedup vs baseline: 1.2270x; 1.0312x over previous
#include <cuda_runtime.h>
#include <cuda_bf16.h>
#include <cstdint>

#define DIM 512
#define NH 8
#define HD 64
#define MAXM 8192
#define KTOT 512

// ---------------------------------------------------------------------------
// Scratch (allocation-free rule: __device__ globals)
// ---------------------------------------------------------------------------
__device__ uint32_t g_xt[MAXM * DIM];
__device__ uint32_t g_wqt[3 * DIM * DIM];
__device__ uint32_t g_wpt[DIM * DIM];
__device__ uint32_t g_qt[MAXM * DIM];      // q head-major, x hd^-.5*log2e, sig16
__device__ uint32_t g_kt[MAXM * DIM];      // k head-major, sig16
__device__ uint32_t g_vt[MAXM * DIM];      // V TRANSPOSED per (b,h): [d][key tau16]
__device__ uint32_t g_at[MAXM * DIM];      // attn out, tf32, sigma-perm

// ---------------------------------------------------------------------------
// helpers (compute_103-safe: sm_80 baseline PTX)
// ---------------------------------------------------------------------------
__device__ __forceinline__ uint32_t smem_u32(const void* p) {
    uint32_t a;
    asm("{ .reg .u64 t; cvta.to.shared.u64 t, %1; cvt.u32.u64 %0, t; }"
        : "=r"(a) : "l"(p));
    return a;
}
__device__ __forceinline__ uint32_t tf32r(float v) {
    uint32_t r;
    asm("cvt.rna.tf32.f32 %0, %1;" : "=r"(r) : "f"(v));
    return r;
}
__device__ __forceinline__ float ex2f(float x) {
    float r;
    asm("ex2.approx.f32 %0, %1;" : "=f"(r) : "f"(x));
    return r;
}
__device__ __forceinline__ int sig16(int k) {
    return (k & ~15) | (((k & 3) << 2) | ((k >> 2) & 3));
}
// within-16 key permutation for transposed V: key 8b+2c+r -> pos 4c+2b+r
__device__ __forceinline__ int tau16(int n) {
    return (n & ~15) | (((n >> 1) & 3) * 4 + ((n >> 3) & 1) * 2 + (n & 1));
}
__device__ __forceinline__ void mmatf(float* c, uint32_t a0, uint32_t a1,
                                      uint32_t a2, uint32_t a3,
                                      uint32_t b0, uint32_t b1) {
    asm volatile(
        "mma.sync.aligned.m16n8k8.row.col.f32.tf32.tf32.f32 "
        "{%0,%1,%2,%3}, {%4,%5,%6,%7}, {%8,%9}, {%0,%1,%2,%3};"
        : "+f"(c[0]), "+f"(c[1]), "+f"(c[2]), "+f"(c[3])
        : "r"(a0), "r"(a1), "r"(a2), "r"(a3), "r"(b0), "r"(b1));
}
__device__ __forceinline__ void cpa16(uint32_t saddr, const void* g) {
    asm volatile("cp.async.cg.shared.global [%0], [%1], 16;"
                 :: "r"(saddr), "l"(g) : "memory");
}
#define CPA_COMMIT() asm volatile("cp.async.commit_group;" ::: "memory")
#define CPA_WAIT1()  asm volatile("cp.async.wait_group 1;" ::: "memory")
#define CPA_WAIT0()  asm volatile("cp.async.wait_group 0;" ::: "memory")

// ---------------------------------------------------------------------------
// Prep: fp32 -> tf32 (rna), sigma-permuted. One thread per 16-element block
// (sigma within a 16-block is a 4x4 transpose -> 4x LDG.128 + 4x STG.128).
// ---------------------------------------------------------------------------
__global__ void prep(const float* __restrict__ x, const float* __restrict__ wq,
                     const float* __restrict__ wp, int nx) {
    const int NWQ = 3 * DIM * DIM, NWP = DIM * DIM;
    int i = (blockIdx.x * 256 + threadIdx.x) * 16;
    const float* src;
    uint32_t* out;
    int j;
    if (i < nx)                  { src = x;  out = g_xt;  j = i; }
    else if (i < nx + NWQ)       { j = i - nx;       src = wq; out = g_wqt; }
    else if (i < nx + NWQ + NWP) { j = i - nx - NWQ; src = wp; out = g_wpt; }
    else return;

    float4 r0 = *(const float4*)(src + j);
    float4 r1 = *(const float4*)(src + j + 4);
    float4 r2 = *(const float4*)(src + j + 8);
    float4 r3 = *(const float4*)(src + j + 12);
    uint4 o;
    o.x = tf32r(r0.x); o.y = tf32r(r1.x); o.z = tf32r(r2.x); o.w = tf32r(r3.x);
    *(uint4*)(out + j)      = o;
    o.x = tf32r(r0.y); o.y = tf32r(r1.y); o.z = tf32r(r2.y); o.w = tf32r(r3.y);
    *(uint4*)(out + j + 4)  = o;
    o.x = tf32r(r0.z); o.y = tf32r(r1.z); o.z = tf32r(r2.z); o.w = tf32r(r3.z);
    *(uint4*)(out + j + 8)  = o;
    o.x = tf32r(r0.w); o.y = tf32r(r1.w); o.z = tf32r(r2.w); o.w = tf32r(r3.w);
    *(uint4*)(out + j + 12) = o;
}

// ---------------------------------------------------------------------------
// TF32 GEMM, 128 threads, CTA tile 128(M) x 64(N), warp tile 32x64,
// K chunk 32, 2-stage cp.async pipeline (R8 structure, measured best).
// MODE 0 epilogue -> q/k tf32 sig16 head-major; V TRANSPOSED tau16 tf32.
// ---------------------------------------------------------------------------
#define GSTG2 24576
#define GEMM_SMEM (2 * GSTG2)
#define NCHUNK (KTOT / 32)
#define QSCALE (0.125f * 1.4426950408889634f)

template<int MODE>
__global__ __launch_bounds__(128, 3)
void gemm_tc(float* __restrict__ C, int M, int NC,
             const int* __restrict__ Hp, const int* __restrict__ Wp)
{
    extern __shared__ __align__(16) char dsm[];
    const uint32_t smb = smem_u32(dsm);

    const int tid = threadIdx.x;
    const int wid = tid >> 5;
    const int lane = tid & 31;
    const int gID = lane >> 2, cA = lane & 3;

    const int m0 = blockIdx.y * 128;
    const int n0 = blockIdx.x * 64;

    const uint32_t* A = MODE ? g_at : g_xt;
    const uint32_t* B = MODE ? g_wpt : g_wqt;

    auto issue = [&](int stg, int chunk) {
        const uint32_t sb = smb + stg * GSTG2;
        const int k0 = chunk * 32;
#pragma unroll
        for (int t = 0; t < 8; t++) {            // A: 128 rows x 8 units
            int idx = t * 128 + tid;
            int row = idx >> 3, u = idx & 7;
            uint32_t so = (uint32_t)row * 128 + ((u + 4 * row) & 7) * 16;
            cpa16(sb + so, A + (size_t)(m0 + row) * KTOT + k0 + u * 4);
        }
#pragma unroll
        for (int t = 0; t < 4; t++) {            // B: 64 rows x 8 units
            int idx = t * 128 + tid;
            int row = idx >> 3, u = idx & 7;
            uint32_t so = (uint32_t)row * 128 + ((u + 4 * row) & 7) * 16;
            cpa16(sb + 16384 + so, B + (size_t)(n0 + row) * KTOT + k0 + u * 4);
        }
        CPA_COMMIT();
    };

    float acc[2][8][4];
#pragma unroll
    for (int i = 0; i < 2; i++)
#pragma unroll
        for (int j = 0; j < 8; j++)
#pragma unroll
            for (int k = 0; k < 4; k++) acc[i][j][k] = 0.f;

    issue(0, 0);

    for (int chunk = 0; chunk < NCHUNK; chunk++) {
        if (chunk + 1 < NCHUNK) { issue((chunk + 1) & 1, chunk + 1); CPA_WAIT1(); }
        else                    { CPA_WAIT0(); }
        __syncthreads();

        const char* aC = dsm + (chunk & 1) * GSTG2;
        const char* bC = aC + 16384;

#pragma unroll
        for (int g = 0; g < 2; g++) {
            uint4 alo[2], ahi[2];
#pragma unroll
            for (int mt = 0; mt < 2; mt++) {
                int rA = wid * 32 + mt * 16 + gID;
                uint32_t u = (uint32_t)((g * 4 + cA + 4 * rA) & 7) * 16;
                alo[mt] = *(const uint4*)(aC + rA * 128 + u);
                ahi[mt] = *(const uint4*)(aC + (rA + 8) * 128 + u);
            }
#pragma unroll
            for (int ng = 0; ng < 8; ng++) {
                int rB = ng * 8 + gID;
                uint32_t u = (uint32_t)((g * 4 + cA + 4 * rB) & 7) * 16;
                uint4 bb = *(const uint4*)(bC + rB * 128 + u);
#pragma unroll
                for (int mt = 0; mt < 2; mt++) {
                    mmatf(acc[mt][ng], alo[mt].x, ahi[mt].x, alo[mt].y, ahi[mt].y,
                          bb.x, bb.y);
                    mmatf(acc[mt][ng], alo[mt].z, ahi[mt].z, alo[mt].w, ahi[mt].w,
                          bb.z, bb.w);
                }
            }
        }
        __syncthreads();
    }

    // ---------------- epilogue ----------------
    int Nseq = 0;
    if (MODE == 0) Nseq = (*Wp) * (*Hp);

#pragma unroll
    for (int mt = 0; mt < 2; mt++) {
#pragma unroll
        for (int ro = 0; ro < 2; ro++) {
            const int m = m0 + wid * 32 + mt * 16 + ro * 8 + gID;
            int b = 0, n = 0;
            if (MODE == 0) { b = m / Nseq; n = m - b * Nseq; }
#pragma unroll
            for (int nt = 0; nt < 8; nt++) {
                const int d = n0 + nt * 8 + cA * 2;
                float a0 = acc[mt][nt][ro * 2 + 0];
                float a1 = acc[mt][nt][ro * 2 + 1];
                if (MODE == 0) {
                    const int which = d >> 9;
                    const int h = (d >> 6) & 7;
                    const int e = d & 63;
                    if (which == 0) {
                        size_t off = ((size_t)(b * NH + h) * Nseq + n) * HD;
                        g_qt[off + sig16(e)]     = tf32r(a0 * QSCALE);
                        g_qt[off + sig16(e + 1)] = tf32r(a1 * QSCALE);
                    } else if (which == 1) {
                        size_t off = ((size_t)(b * NH + h) * Nseq + n) * HD;
                        g_kt[off + sig16(e)]     = tf32r(a0);
                        g_kt[off + sig16(e + 1)] = tf32r(a1);
                    } else {
                        // V transposed: [d][key tau16] per (b,h)
                        size_t vb = (size_t)(b * NH + h) * Nseq * HD + tau16(n);
                        g_vt[vb + (size_t)e * Nseq]       = tf32r(a0);
                        g_vt[vb + (size_t)(e + 1) * Nseq] = tf32r(a1);
                    }
                } else {
                    *(float2*)(C + (size_t)m * NC + d) = make_float2(a0, a1);
                }
            }
        }
    }
}

// ---------------------------------------------------------------------------
// Flash attention, 128 threads, 64 Q rows per CTA (4 warps x 16 rows).
// S = Q K^T tf32 (log2e pre-scaled); factorized decay bias (W==32 fast path);
// PV in PURE tf32: S-accumulator regs reused directly as A-fragments
// (key slot perm: col 2cA -> slot cA, col 2cA+1 -> slot cA+4), V stored
// transposed + tau16-permuted so B-fragments are single swizzled LDS.128.
// ---------------------------------------------------------------------------
#define VOFF 16384
#define ASTG2 32768
#define ATTN_SMEM (2 * ASTG2 + 256 + 512 + 512)

__global__ __launch_bounds__(128, 3)
void attn_mma(const float* __restrict__ log_decay, int M,
              const int* __restrict__ Hp, const int* __restrict__ Wp)
{
    extern __shared__ __align__(16) char sm[];
    const uint32_t smb = smem_u32(sm);
    float* Ts  = (float*)(sm + 2 * ASTG2);
    int*   krs = (int*)(sm + 2 * ASTG2 + 256);
    int*   kcs = (int*)(sm + 2 * ASTG2 + 768);

    const int Wv = *Wp, Hv = *Hp;
    const int Nseq = Wv * Hv;
    const int ntiles = Nseq / 64;
    const bool fast = (Wv == 32);
    const int h = blockIdx.y;
    const int m0 = blockIdx.x * 64;
    const int b = m0 / Nseq;
    const int n0 = m0 - b * Nseq;

    const int tid = threadIdx.x, w = tid >> 5, lane = tid & 31;
    const int gID = lane >> 2, cA = lane & 3, t2 = cA * 2;

    const float decay = log1pf(__expf(log_decay[h]));
    if (tid < 64) Ts[tid] = __expf(-decay * (float)tid);

    const size_t bh_off = (size_t)(b * NH + h) * Nseq * HD;
    const uint32_t* Qt_g = g_qt + bh_off + (size_t)n0 * HD;
    const uint32_t* Kt_g = g_kt + bh_off;
    const uint32_t* Vt_g = g_vt + bh_off;    // [d][key tau16], row stride Nseq

    const int nr0 = n0 + w * 16 + gID;
    const int qr0 = nr0 / Wv, qc0 = nr0 - qr0 * Wv;
    const int nr1 = nr0 + 8;
    const int qr1 = nr1 / Wv, qc1 = nr1 - qr1 * Wv;

    // ---- stage Q (64 rows x 16 units, swizzled; aliases stage-0 K) ----
#pragma unroll
    for (int i = 0; i < 8; i++) {
        int idx = i * 128 + tid;
        int row = idx >> 4, u = idx & 15;
        cpa16(smb + (uint32_t)row * 256 + ((u + 4 * row) & 15) * 16,
              Qt_g + (size_t)row * HD + u * 4);
    }
    CPA_COMMIT();
    CPA_WAIT0();
    __syncthreads();

    // ---- Q fragments (persistent, tf32) ----
    uint4 qlo[4], qhi[4];
    {
        const int r0 = w * 16 + gID;
#pragma unroll
        for (int g = 0; g < 4; g++) {
            uint32_t u = (uint32_t)((g * 4 + cA + 4 * r0) & 15) * 16;
            qlo[g] = *(const uint4*)(sm + r0 * 256 + u);
            qhi[g] = *(const uint4*)(sm + (r0 + 8) * 256 + u);
        }
    }

    // ---- per-thread column decay factors (fixed across tiles, W==32) ----
    float tc0[8], tc1[8];
#pragma unroll
    for (int j = 0; j < 8; j++) {
        int kcol = (j >> 1) * 8 + t2 + (j & 1);
        tc0[j] = Ts[abs(qc0 - kcol)];
        tc1[j] = Ts[abs(qc1 - kcol)];
    }
    __syncthreads();   // Q frag / Ts reads done before stage-0 overwrite

    auto issue_kv = [&](int stg, int t0) {
        const uint32_t sb = smb + stg * ASTG2;
#pragma unroll
        for (int i = 0; i < 8; i++) {            // K: 64 rows x 16 units
            int idx = i * 128 + tid;
            int row = idx >> 4, u = idx & 15;
            cpa16(sb + (uint32_t)row * 256 + ((u + 4 * row) & 15) * 16,
                  Kt_g + (size_t)(t0 + row) * HD + u * 4);
        }
#pragma unroll
        for (int i = 0; i < 8; i++) {            // Vt: 64 d-rows x 16 units
            int idx = i * 128 + tid;
            int row = idx >> 4, u = idx & 15;
            cpa16(sb + VOFF + (uint32_t)row * 256 + ((u + 4 * row) & 15) * 16,
                  Vt_g + (size_t)row * Nseq + t0 + u * 4);
        }
        if (!fast && tid < 64) {
            int kn = t0 + tid;
            int kr = kn / Wv;
            krs[stg * 64 + tid] = kr;
            kcs[stg * 64 + tid] = kn - kr * Wv;
        }
        CPA_COMMIT();
    };

    float o[8][4];
#pragma unroll
    for (int i = 0; i < 8; i++)
#pragma unroll
        for (int j = 0; j < 4; j++) o[i][j] = 0.f;
    float lsum0 = 0.f, lsum1 = 0.f;

    issue_kv(0, 0);

    for (int it = 0; it < ntiles; it++) {
        const int t0 = it * 64;
        if (it + 1 < ntiles) { issue_kv((it + 1) & 1, t0 + 64); CPA_WAIT1(); }
        else                 { CPA_WAIT0(); }
        __syncthreads();

        const char* sbc = sm + (it & 1) * ASTG2;

        // ---- S = Q K^T (tf32, scores pre-scaled by log2e) ----
        float s[8][4];
#pragma unroll
        for (int i = 0; i < 8; i++)
#pragma unroll
            for (int j = 0; j < 4; j++) s[i][j] = 0.f;

#pragma unroll
        for (int g = 0; g < 4; g++) {
#pragma unroll
            for (int ng = 0; ng < 8; ng++) {
                int rb = ng * 8 + gID;
                uint32_t u = (uint32_t)((g * 4 + cA + 4 * rb) & 15) * 16;
                uint4 kb = *(const uint4*)(sbc + rb * 256 + u);
                mmatf(s[ng], qlo[g].x, qhi[g].x, qlo[g].y, qhi[g].y, kb.x, kb.y);
                mmatf(s[ng], qlo[g].z, qhi[g].z, qlo[g].w, qhi[g].w, kb.z, kb.w);
            }
        }

        // ---- bias + exp -> P as tf32 A-fragments (a0,a1,a2,a3) ----
        uint32_t tp[8][4];
        if (fast) {
            const int r0 = t0 >> 5;
            const float tr00 = Ts[abs(qr0 - r0)], tr01 = Ts[abs(qr0 - r0 - 1)];
            const float tr10 = Ts[abs(qr1 - r0)], tr11 = Ts[abs(qr1 - r0 - 1)];
#pragma unroll
            for (int nt = 0; nt < 8; nt++) {
                const int jj = (nt & 3) * 2;
                const float f0 = (nt < 4) ? tr00 : tr01;
                const float f1 = (nt < 4) ? tr10 : tr11;
                float p00 = ex2f(s[nt][0]) * (tc0[jj]     * f0);
                float p01 = ex2f(s[nt][1]) * (tc0[jj + 1] * f0);
                float p10 = ex2f(s[nt][2]) * (tc1[jj]     * f1);
                float p11 = ex2f(s[nt][3]) * (tc1[jj + 1] * f1);
                lsum0 += p00 + p01;
                lsum1 += p10 + p11;
                tp[nt][0] = tf32r(p00); tp[nt][1] = tf32r(p10);
                tp[nt][2] = tf32r(p01); tp[nt][3] = tf32r(p11);
            }
        } else {
            const int* kr_t = krs + (it & 1) * 64;
            const int* kc_t = kcs + (it & 1) * 64;
#pragma unroll
            for (int nt = 0; nt < 8; nt++) {
                const int c0 = nt * 8 + t2, c1 = c0 + 1;
                const int kr0 = kr_t[c0], kc0 = kc_t[c0];
                const int kr1 = kr_t[c1], kc1 = kc_t[c1];
                float p00 = ex2f(s[nt][0]) * Ts[abs(qr0 - kr0) + abs(qc0 - kc0)];
                float p01 = ex2f(s[nt][1]) * Ts[abs(qr0 - kr1) + abs(qc0 - kc1)];
                float p10 = ex2f(s[nt][2]) * Ts[abs(qr1 - kr0) + abs(qc1 - kc0)];
                float p11 = ex2f(s[nt][3]) * Ts[abs(qr1 - kr1) + abs(qc1 - kc1)];
                lsum0 += p00 + p01;
                lsum1 += p10 + p11;
                tp[nt][0] = tf32r(p00); tp[nt][1] = tf32r(p10);
                tp[nt][2] = tf32r(p01); tp[nt][3] = tf32r(p11);
            }
        }

        // ---- O += P V (pure tf32; B = transposed tau16 V, LDS.128) ----
#pragma unroll
        for (int gp = 0; gp < 4; gp++) {
            const uint32_t* A0 = tp[2 * gp];
            const uint32_t* A1 = tp[2 * gp + 1];
#pragma unroll
            for (int ng = 0; ng < 8; ng++) {
                int row = ng * 8 + gID;
                uint32_t u = (uint32_t)((gp * 4 + cA + 4 * row) & 15) * 16;
                uint4 bb = *(const uint4*)(sbc + VOFF + row * 256 + u);
                mmatf(o[ng], A0[0], A0[1], A0[2], A0[3], bb.x, bb.y);
                mmatf(o[ng], A1[0], A1[1], A1[2], A1[3], bb.z, bb.w);
            }
        }
        __syncthreads();
    }

    // ---- normalize + write tf32 sigma-perm ----
    lsum0 += __shfl_xor_sync(0xFFFFFFFFu, lsum0, 1);
    lsum0 += __shfl_xor_sync(0xFFFFFFFFu, lsum0, 2);
    lsum1 += __shfl_xor_sync(0xFFFFFFFFu, lsum1, 1);
    lsum1 += __shfl_xor_sync(0xFFFFFFFFu, lsum1, 2);
    const float inv0 = 1.f / lsum0, inv1 = 1.f / lsum1;

    const size_t rb0 = (size_t)(m0 + w * 16 + gID) * DIM;
    const size_t rb1 = rb0 + 8 * DIM;
#pragma unroll
    for (int nt = 0; nt < 8; nt++) {
        const int col = h * HD + nt * 8 + t2;
        g_at[rb0 + sig16(col)]     = tf32r(o[nt][0] * inv0);
        g_at[rb0 + sig16(col + 1)] = tf32r(o[nt][1] * inv0);
        g_at[rb1 + sig16(col)]     = tf32r(o[nt][2] * inv1);
        g_at[rb1 + sig16(col + 1)] = tf32r(o[nt][3] * inv1);
    }
}

// ---------------------------------------------------------------------------
extern "C" void kernel_launch(void* const* d_in, const int* in_sizes, int n_in,
                              void* d_out, int out_size)
{
    const float* x      = (const float*)d_in[0];
    const float* w_qkv  = (const float*)d_in[1];
    const float* w_proj = (const float*)d_in[2];
    const float* ldec   = (const float*)d_in[3];
    const int* Hp = (const int*)d_in[4];
    const int* Wp = (const int*)d_in[5];

    const int M = in_sizes[0] / DIM;

    cudaFuncSetAttribute(gemm_tc<0>, cudaFuncAttributeMaxDynamicSharedMemorySize, GEMM_SMEM);
    cudaFuncSetAttribute(gemm_tc<1>, cudaFuncAttributeMaxDynamicSharedMemorySize, GEMM_SMEM);
    cudaFuncSetAttribute(attn_mma,   cudaFuncAttributeMaxDynamicSharedMemorySize, ATTN_SMEM);

    // 0) fp32 -> tf32 (sigma-permuted), 16 elems/thread
    {
        int total = M * DIM + 3 * DIM * DIM + DIM * DIM;
        int blocks = (total / 16 + 255) / 256;
        prep<<<blocks, 256>>>(x, w_qkv, w_proj, M * DIM);
    }
    // 1) QKV projection (tf32) -> q/k sig16 + V transposed tau16
    gemm_tc<0><<<dim3(3 * DIM / 64, M / 128), 128, GEMM_SMEM>>>(nullptr, M, 3 * DIM, Hp, Wp);
    // 2) spatial-decay flash attention (pure tf32 S and PV)
    attn_mma<<<dim3(M / 64, NH), 128, ATTN_SMEM>>>(ldec, M, Hp, Wp);
    // 3) output projection (tf32)
    gemm_tc<1><<<dim3(DIM / 64, M / 128), 128, GEMM_SMEM>>>((float*)d_out, M, DIM,
                                                            nullptr, nullptr);
}